// round 10
// baseline (speedup 1.0000x reference)
#include <cuda_runtime.h>
#include <cuda_bf16.h>
#include <cstdint>

// ---------------------------------------------------------------------------
// Problem dims
// ---------------------------------------------------------------------------
#define NIN   128
#define NHID  256
#define NDEC  512
#define NOUT  10
#define BATCH 32
#define NSET  4096

#define TM       64                     // rows per tile
#define NTILES   (BATCH * NSET / TM)    // 2048
#define THREADS  256                    // 8 warps: 2 (row halves of 32) x 4 (col quarters)
#define GRID_ENC 148                    // persistent: 1 CTA per SM (regs: c + c_lo)

// Weight image: k-chunks of 32. chunk = hi bf16 (16KB) + lo e4m3 x4096 (8KB)
#define CHUNK_BYTES 24576
#define CHUNK_HI    16384
#define NCHUNKS     20                  // L1:4  L2:8  L3:8  (contiguous)
#define IMG_BYTES   (NCHUNKS * CHUNK_BYTES)

#define LO_INV (1.0f / 4096.0f)
#define LO_SCL 4096.0f

// SMEM layout (bytes)
#define SMEM_A     0                    // 64 rows x 512B bf16, XOR-swizzled
#define SMEM_AFP8  32768                // 64 rows x 256B e4m3, XOR-swizzled
#define SMEM_W     49152                // 2 slots x 24KB ring
#define SMEM_BIAS  98304                // 256 floats
#define SMEM_RED   99328                // 2 x 256 floats
#define SMEM_TOTAL 101376

// ---------------------------------------------------------------------------
// Device globals (static; fully rewritten every launch)
// ---------------------------------------------------------------------------
__device__ __align__(128) uint8_t g_wimg[IMG_BYTES];
__device__ float g_partial[NTILES * NHID];

// ---------------------------------------------------------------------------
// PTX helpers
// ---------------------------------------------------------------------------
__device__ __forceinline__ uint32_t smem_u32(const void* p) {
    uint32_t a;
    asm("{ .reg .u64 t; cvta.to.shared.u64 t, %1; cvt.u32.u64 %0, t; }" : "=r"(a) : "l"(p));
    return a;
}

__device__ __forceinline__ void ldsm4(uint32_t r[4], uint32_t addr) {
    asm volatile("ldmatrix.sync.aligned.m8n8.x4.shared.b16 {%0,%1,%2,%3}, [%4];"
        : "=r"(r[0]), "=r"(r[1]), "=r"(r[2]), "=r"(r[3]) : "r"(addr));
}

__device__ __forceinline__ void mma16(float c[4], const uint32_t a[4], uint32_t b0, uint32_t b1) {
    asm volatile(
        "mma.sync.aligned.m16n8k16.row.col.f32.bf16.bf16.f32 "
        "{%0,%1,%2,%3},{%4,%5,%6,%7},{%8,%9},{%0,%1,%2,%3};"
        : "+f"(c[0]), "+f"(c[1]), "+f"(c[2]), "+f"(c[3])
        : "r"(a[0]), "r"(a[1]), "r"(a[2]), "r"(a[3]), "r"(b0), "r"(b1));
}

__device__ __forceinline__ void mma32f8(float c[4], const uint32_t a[4], uint32_t b0, uint32_t b1) {
    asm volatile(
        "mma.sync.aligned.m16n8k32.row.col.f32.e4m3.e4m3.f32 "
        "{%0,%1,%2,%3},{%4,%5,%6,%7},{%8,%9},{%0,%1,%2,%3};"
        : "+f"(c[0]), "+f"(c[1]), "+f"(c[2]), "+f"(c[3])
        : "r"(a[0]), "r"(a[1]), "r"(a[2]), "r"(a[3]), "r"(b0), "r"(b1));
}

// pack two fp32 -> e4m3x2 (low byte = v0, high byte = v1)
__device__ __forceinline__ uint16_t f2e4m3x2(float v0, float v1) {
    uint16_t u;
    asm("cvt.rn.satfinite.e4m3x2.f32 %0, %1, %2;" : "=h"(u) : "f"(v1), "f"(v0));
    return u;
}

#define CP16(dst, src) \
    asm volatile("cp.async.cg.shared.global [%0], [%1], 16;" :: "r"(dst), "l"(src))
#define CP_COMMIT() asm volatile("cp.async.commit_group;" ::: "memory")
#define CP_WAIT1()  asm volatile("cp.async.wait_group 1;"  ::: "memory")

// hi B image swizzle (64B rows): bits 4-5 of the k-byte-offset
__device__ __forceinline__ uint32_t bmask(int n) { return ((uint32_t)(n >> 1) & 3u) << 4; }
// lo B image swizzle (32B rows): bit 4 of the k-byte-offset
__device__ __forceinline__ uint32_t lomask(int n) { return ((uint32_t)(n >> 2) & 1u) << 4; }

// ---------------------------------------------------------------------------
// Weight pre-convert: fp32 W[K,256] -> per-chunk [hi bf16 swizzled | lo e4m3*4096]
// ---------------------------------------------------------------------------
__global__ void __launch_bounds__(256)
convert_weights(const float* __restrict__ W1, const float* __restrict__ W2,
                const float* __restrict__ W3)
{
    int idx = blockIdx.x * 256 + threadIdx.x;    // 0 .. 81919 (hi uint32 slots)
    int chunk = idx >> 12;                       // 4096 slots per chunk
    int rem   = idx & 4095;
    int n     = rem >> 4;                        // 0..255
    int s     = rem & 15;                        // uint32 slot within 64B hi row

    const float* W; int kbase;
    if (chunk < 4)       { W = W1; kbase = chunk * 32; }
    else if (chunk < 12) { W = W2; kbase = (chunk - 4) * 32; }
    else                 { W = W3; kbase = (chunk - 12) * 32; }

    // inverse hi swizzle: stored byte = (k*2) ^ bm  =>  k*2 = (4s) ^ bm
    uint32_t bm = bmask(n);
    int k0 = (int)((((uint32_t)(4 * s)) ^ bm) >> 1);   // even; pair (k0, k0+1)
    float w0 = W[(kbase + k0) * 256 + n];
    float w1 = W[(kbase + k0 + 1) * 256 + n];

    __nv_bfloat16 h0 = __float2bfloat16(w0);
    __nv_bfloat16 h1 = __float2bfloat16(w1);
    float r0f = (w0 - __bfloat162float(h0)) * LO_SCL;
    float r1f = (w1 - __bfloat162float(h1)) * LO_SCL;

    uint32_t hi = ((uint32_t)*reinterpret_cast<uint16_t*>(&h1) << 16) |
                   (uint32_t)*reinterpret_cast<uint16_t*>(&h0);
    uint16_t lo = f2e4m3x2(r0f, r1f);            // low byte = k0, high = k0+1

    uint8_t* cb = g_wimg + (size_t)chunk * CHUNK_BYTES;
    *(uint32_t*)(cb + n * 64 + 4 * s) = hi;
    *(uint16_t*)(cb + CHUNK_HI + n * 32 + (((uint32_t)k0) ^ lomask(n))) = lo;
}

// ---------------------------------------------------------------------------
// Encoder: persistent, TM=64 tiles, 3 fused layers. hi = bf16 k16 HMMA,
// lo = e4m3 k32 QMMA into separate accumulators, folded *1/4096 at epilogue.
// R8-proven 2-slot ring: wait1 / barrier / mma / barrier / refill(g+2 mod 20).
// ---------------------------------------------------------------------------
__global__ void __launch_bounds__(THREADS, 1)
encoder_kernel(const float* __restrict__ x,
               const float* __restrict__ b1, const float* __restrict__ b2,
               const float* __restrict__ b3)
{
    extern __shared__ char smem[];
    const uint32_t sb = smem_u32(smem);
    const int tid  = threadIdx.x;
    const int lane = tid & 31;
    const int wid  = tid >> 5;
    const int wm   = wid >> 2;          // 0..1  (row half, 32 rows)
    const int wn   = wid & 3;           // 0..3  (col quarter, 64 cols)
    float* bias_s = (float*)(smem + SMEM_BIAS);
    float* red    = (float*)(smem + SMEM_RED);

    // --- prologue: prefetch chunks 0,1 ---
#pragma unroll
    for (int c0 = 0; c0 < 2; c0++) {
        const uint8_t* src = g_wimg + (size_t)c0 * CHUNK_BYTES;
        uint32_t dst = sb + SMEM_W + (uint32_t)c0 * CHUNK_BYTES;
#pragma unroll
        for (int i = 0; i < 6; i++)
            CP16(dst + (tid + i * 256) * 16, src + (tid + i * 256) * 16);
        CP_COMMIT();
    }

    // --- per-thread ldmatrix address precompute ---
    uint32_t a_base[2], a8_base[2], a_xm[2];
    {
        int r0 = wm * 32 + (lane & 15);
#pragma unroll
        for (int mt = 0; mt < 2; mt++) {
            int r = r0 + mt * 16;
            a_base[mt]  = sb + SMEM_A    + (uint32_t)(r * 512);
            a8_base[mt] = sb + SMEM_AFP8 + (uint32_t)(r * 256);
            a_xm[mt]    = ((uint32_t)(r & 7)) << 4;
        }
    }
    const uint32_t a_h16 = (uint32_t)(lane >> 4) * 16;   // k-half selector (A, hi & fp8)
    uint32_t b_off[4], b_xm[4], bl_off[4], bl_xm[4];
    {
        int n0 = wn * 64 + (lane & 7) + ((lane >> 4) << 3);
#pragma unroll
        for (int q = 0; q < 4; q++) {
            int n = n0 + q * 16;
            b_off[q]  = (uint32_t)(n * 64);
            b_xm[q]   = bmask(n);
            bl_off[q] = (uint32_t)(n * 32);
            bl_xm[q]  = lomask(n);
        }
    }
    const uint32_t b_h16 = ((uint32_t)(lane >> 3) & 1) * 16;

    const float* biases[3] = { b1, b2, b3 };
    const int    ncs[3]    = { 4, 8, 8 };
    const int    gg = lane >> 2, t = lane & 3;

    for (int tile = blockIdx.x; tile < NTILES; tile += GRID_ENC) {
        // --- stage x tile: fp32 -> bf16 A (512B rows) AND e4m3 A (256B rows) ---
        {
            const float4* xt = (const float4*)(x + (size_t)tile * TM * NIN);
#pragma unroll
            for (int i = tid; i < TM * NIN / 4; i += THREADS) {
                float4 v = xt[i];
                int p = i * 4;
                int r = p >> 7, cc = p & 127;
                const uint32_t xm = ((uint32_t)(r & 7)) << 4;
                uint32_t off = ((uint32_t)(r * 512 + cc * 2)) ^ xm;
                __nv_bfloat162 lo2 = __floats2bfloat162_rn(v.x, v.y);
                __nv_bfloat162 hi2 = __floats2bfloat162_rn(v.z, v.w);
                uint2 u;
                u.x = *reinterpret_cast<uint32_t*>(&lo2);
                u.y = *reinterpret_cast<uint32_t*>(&hi2);
                *(uint2*)(smem + SMEM_A + off) = u;
                uint32_t f8 = (uint32_t)f2e4m3x2(v.x, v.y) |
                              ((uint32_t)f2e4m3x2(v.z, v.w) << 16);
                *(uint32_t*)(smem + SMEM_AFP8 + r * 256 + (((uint32_t)cc) ^ xm)) = f8;
            }
        }
        __syncthreads();                 // x staged before layer-1 MMAs

        int g = 0;                       // within-tile chunk index (0..19)
        for (int L = 0; L < 3; L++) {
            bias_s[tid] = biases[L][tid];

            float c[2][8][4], cl[2][8][4];
#pragma unroll
            for (int mt = 0; mt < 2; mt++)
#pragma unroll
                for (int nt = 0; nt < 8; nt++)
#pragma unroll
                    for (int e = 0; e < 4; e++) { c[mt][nt][e] = 0.f; cl[mt][nt][e] = 0.f; }

            const int nc = ncs[L];
            for (int lk = 0; lk < nc; lk++, g++) {
                CP_WAIT1();              // chunk g resident (1 pending: g+1)
                __syncthreads();

                const uint32_t wslot = sb + SMEM_W + (uint32_t)(g & 1) * CHUNK_BYTES;

                // ---- hi: bf16 k16 ----
#pragma unroll
                for (int ks = 0; ks < 2; ks++) {
                    uint32_t a[2][4];
                    const uint32_t kkA = (uint32_t)(lk * 64 + ks * 32) + a_h16;
#pragma unroll
                    for (int mt = 0; mt < 2; mt++)
                        ldsm4(a[mt], a_base[mt] + (kkA ^ a_xm[mt]));

                    const uint32_t kkB = (uint32_t)(ks * 32) + b_h16;
#pragma unroll
                    for (int q = 0; q < 4; q++) {
                        uint32_t bh[4];
                        ldsm4(bh, wslot + b_off[q] + (kkB ^ b_xm[q]));
                        const int nt0 = 2 * q;
#pragma unroll
                        for (int mt = 0; mt < 2; mt++) {
                            mma16(c[mt][nt0],     a[mt], bh[0], bh[1]);
                            mma16(c[mt][nt0 + 1], a[mt], bh[2], bh[3]);
                        }
                    }
                }

                // ---- lo: e4m3 k32 (whole chunk in one k-step) ----
                {
                    uint32_t a8[2][4];
                    const uint32_t kkA8 = (uint32_t)(lk * 32) + a_h16;
#pragma unroll
                    for (int mt = 0; mt < 2; mt++)
                        ldsm4(a8[mt], a8_base[mt] + (kkA8 ^ a_xm[mt]));
#pragma unroll
                    for (int q = 0; q < 4; q++) {
                        uint32_t bl[4];
                        ldsm4(bl, wslot + CHUNK_HI + bl_off[q] + (b_h16 ^ bl_xm[q]));
                        const int nt0 = 2 * q;
#pragma unroll
                        for (int mt = 0; mt < 2; mt++) {
                            mma32f8(cl[mt][nt0],     a8[mt], bl[0], bl[1]);
                            mma32f8(cl[mt][nt0 + 1], a8[mt], bl[2], bl[3]);
                        }
                    }
                }

                __syncthreads();         // all warps done reading slot g&1
                {                        // refill with chunk (g+2) mod 20 (periodic stream)
                    int nxt = g + 2; if (nxt >= NCHUNKS) nxt -= NCHUNKS;
                    uint32_t dst = sb + SMEM_W + (uint32_t)(g & 1) * CHUNK_BYTES;
                    const uint8_t* src = g_wimg + (size_t)nxt * CHUNK_BYTES;
#pragma unroll
                    for (int i = 0; i < 6; i++)
                        CP16(dst + (tid + i * 256) * 16, src + (tid + i * 256) * 16);
                }
                CP_COMMIT();
            }

            if (L < 2) {
                // epilogue: fold lo, bias + relu -> bf16 A and e4m3 A, in place
#pragma unroll
                for (int mt = 0; mt < 2; mt++) {
                    const int r0 = wm * 32 + mt * 16 + gg;
                    const int r1 = r0 + 8;
                    const uint32_t x0 = ((uint32_t)(r0 & 7)) << 4;
                    const uint32_t x1 = ((uint32_t)(r1 & 7)) << 4;
#pragma unroll
                    for (int nt = 0; nt < 8; nt++) {
                        const int col = wn * 64 + nt * 8 + 2 * t;
                        const float bb0 = bias_s[col], bb1 = bias_s[col + 1];
                        float v0 = fmaxf(c[mt][nt][0] + LO_INV * cl[mt][nt][0] + bb0, 0.f);
                        float v1 = fmaxf(c[mt][nt][1] + LO_INV * cl[mt][nt][1] + bb1, 0.f);
                        float v2 = fmaxf(c[mt][nt][2] + LO_INV * cl[mt][nt][2] + bb0, 0.f);
                        float v3 = fmaxf(c[mt][nt][3] + LO_INV * cl[mt][nt][3] + bb1, 0.f);
                        __nv_bfloat162 p0 = __floats2bfloat162_rn(v0, v1);
                        __nv_bfloat162 p1 = __floats2bfloat162_rn(v2, v3);
                        uint32_t o0 = ((uint32_t)(r0 * 512 + col * 2)) ^ x0;
                        uint32_t o1 = ((uint32_t)(r1 * 512 + col * 2)) ^ x1;
                        *(uint32_t*)(smem + SMEM_A + o0) = *reinterpret_cast<uint32_t*>(&p0);
                        *(uint32_t*)(smem + SMEM_A + o1) = *reinterpret_cast<uint32_t*>(&p1);
                        *(uint16_t*)(smem + SMEM_AFP8 + r0 * 256 + (((uint32_t)col) ^ x0)) =
                            f2e4m3x2(v0, v1);
                        *(uint16_t*)(smem + SMEM_AFP8 + r1 * 256 + (((uint32_t)col) ^ x1)) =
                            f2e4m3x2(v2, v3);
                    }
                }
                __syncthreads();         // epilogue done before next layer's reads
            } else {
                // final: fold lo, bias + relu + column sums over this warp's 32 rows
#pragma unroll
                for (int nt = 0; nt < 8; nt++) {
                    const int col = wn * 64 + nt * 8 + 2 * t;
                    const float bb0 = bias_s[col], bb1 = bias_s[col + 1];
                    float s0 = 0.f, s1 = 0.f;
#pragma unroll
                    for (int mt = 0; mt < 2; mt++) {
                        s0 += fmaxf(c[mt][nt][0] + LO_INV * cl[mt][nt][0] + bb0, 0.f)
                            + fmaxf(c[mt][nt][2] + LO_INV * cl[mt][nt][2] + bb0, 0.f);
                        s1 += fmaxf(c[mt][nt][1] + LO_INV * cl[mt][nt][1] + bb1, 0.f)
                            + fmaxf(c[mt][nt][3] + LO_INV * cl[mt][nt][3] + bb1, 0.f);
                    }
#pragma unroll
                    for (int off = 16; off >= 4; off >>= 1) {
                        s0 += __shfl_down_sync(0xffffffffu, s0, off);
                        s1 += __shfl_down_sync(0xffffffffu, s1, off);
                    }
                    if (lane < 4) {      // lane == t; full 32-row sums for this warp
                        red[wm * 256 + col]     = s0;
                        red[wm * 256 + col + 1] = s1;
                    }
                }
                __syncthreads();
                g_partial[(size_t)tile * NHID + tid] = red[tid] + red[256 + tid];
                __syncthreads();         // red consumed before next tile reuses it
            }
        }
    }
}

// ---------------------------------------------------------------------------
// Fused decoder: mean->square->d1->d2->d3, one CTA per batch, 512 threads.
// ---------------------------------------------------------------------------
__global__ void __launch_bounds__(512, 1)
decoder_kernel(const float* __restrict__ D1, const float* __restrict__ c1,
               const float* __restrict__ D2, const float* __restrict__ c2,
               const float* __restrict__ D3, const float* __restrict__ c3,
               float* __restrict__ out)
{
    __shared__ float p_s[NHID];
    __shared__ float d1_s[NDEC];
    __shared__ float d2_s[NDEC];
    __shared__ float wred[16 * NOUT];
    const int b = blockIdx.x, tid = threadIdx.x;
    const int lane = tid & 31, wrp = tid >> 5;

    if (tid < NHID) {
        const int tiles = NSET / TM;     // 64
        float s = 0.f;
        const float* base = g_partial + (size_t)(b * tiles) * NHID + tid;
#pragma unroll 8
        for (int i = 0; i < tiles; i++) s += base[(size_t)i * NHID];
        const float m = s * (1.0f / NSET);
        p_s[tid] = fmaxf(m * m, 0.f);
    }
    __syncthreads();

    {
        float acc = 0.f;
        const float* w = D1 + tid;
#pragma unroll 8
        for (int k = 0; k < NHID; k++) acc += p_s[k] * w[(size_t)k * NDEC];
        d1_s[tid] = fmaxf(acc + c1[tid], 0.f);
    }
    __syncthreads();

    {
        float acc = 0.f;
        const float* w = D2 + tid;
#pragma unroll 8
        for (int k = 0; k < NDEC; k++) acc += d1_s[k] * w[(size_t)k * NDEC];
        d2_s[tid] = fmaxf(acc + c2[tid], 0.f);
    }
    __syncthreads();

    {
        float part[NOUT];
        const float v = d2_s[tid];
        const float* w = D3 + (size_t)tid * NOUT;
#pragma unroll
        for (int o = 0; o < NOUT; o++) part[o] = v * w[o];
#pragma unroll
        for (int off = 16; off >= 1; off >>= 1)
#pragma unroll
            for (int o = 0; o < NOUT; o++)
                part[o] += __shfl_down_sync(0xffffffffu, part[o], off);
        if (lane == 0)
#pragma unroll
            for (int o = 0; o < NOUT; o++) wred[wrp * NOUT + o] = part[o];
    }
    __syncthreads();
    if (tid < NOUT) {
        float s = 0.f;
#pragma unroll
        for (int w = 0; w < 16; w++) s += wred[w * NOUT + tid];
        out[b * NOUT + tid] = c3[tid] + s;
    }
}

// ---------------------------------------------------------------------------
extern "C" void kernel_launch(void* const* d_in, const int* in_sizes, int n_in,
                              void* d_out, int out_size)
{
    (void)in_sizes; (void)n_in; (void)out_size;
    const float* x  = (const float*)d_in[0];
    const float* W1 = (const float*)d_in[1];
    const float* b1 = (const float*)d_in[2];
    const float* W2 = (const float*)d_in[3];
    const float* b2 = (const float*)d_in[4];
    const float* W3 = (const float*)d_in[5];
    const float* b3 = (const float*)d_in[6];
    const float* D1 = (const float*)d_in[7];
    const float* c1 = (const float*)d_in[8];
    const float* D2 = (const float*)d_in[9];
    const float* c2 = (const float*)d_in[10];
    const float* D3 = (const float*)d_in[11];
    const float* c3 = (const float*)d_in[12];

    cudaFuncSetAttribute(encoder_kernel, cudaFuncAttributeMaxDynamicSharedMemorySize, SMEM_TOTAL);

    convert_weights<<<320, 256>>>(W1, W2, W3);
    encoder_kernel<<<GRID_ENC, THREADS, SMEM_TOTAL>>>(x, b1, b2, b3);
    decoder_kernel<<<BATCH, 512>>>(D1, c1, D2, c2, D3, c3, (float*)d_out);
}

// round 11
// speedup vs baseline: 1.0727x; 1.0727x over previous
#include <cuda_runtime.h>
#include <cuda_fp16.h>
#include <cstdint>

// ---------------------------------------------------------------------------
// Problem dims
// ---------------------------------------------------------------------------
#define NIN   128
#define NHID  256
#define NDEC  512
#define NOUT  10
#define BATCH 32
#define NSET  4096

#define TM       64                     // rows per tile
#define NTILES   (BATCH * NSET / TM)    // 2048
#define THREADS  256                    // 8 warps: 2 (row halves of 32) x 4 (col quarters)
#define GRID_ENC 148                    // persistent: 1 CTA per SM (96 accum regs)

// Weight image: k-chunks of 32. chunk = hi f16 (16KB) + lo f16*1024 (16KB)
#define CHUNK_BYTES 32768
#define CHUNK_HI    16384
#define NCHUNKS     20                  // L1:4  L2:8  L3:8  (contiguous)
#define IMG_BYTES   (NCHUNKS * CHUNK_BYTES)

#define LO_SCL 1024.0f
#define LO_INV (1.0f / 1024.0f)

// SMEM layout (bytes)
#define SMEM_A     0                    // 64 rows x 512B f16, XOR-swizzled
#define SMEM_W     32768                // 2 slots x 32KB ring
#define SMEM_BIAS  98304                // 256 floats
#define SMEM_RED   99328                // 2 x 256 floats
#define SMEM_TOTAL 101376

// ---------------------------------------------------------------------------
// Device globals (static; fully rewritten every launch)
// ---------------------------------------------------------------------------
__device__ __align__(128) uint8_t g_wimg[IMG_BYTES];
__device__ float g_partial[NTILES * NHID];

// ---------------------------------------------------------------------------
// PTX helpers (baseline sm_80-era PTX only: safe at compute_103 target)
// ---------------------------------------------------------------------------
__device__ __forceinline__ uint32_t smem_u32(const void* p) {
    uint32_t a;
    asm("{ .reg .u64 t; cvta.to.shared.u64 t, %1; cvt.u32.u64 %0, t; }" : "=r"(a) : "l"(p));
    return a;
}

__device__ __forceinline__ void ldsm4(uint32_t r[4], uint32_t addr) {
    asm volatile("ldmatrix.sync.aligned.m8n8.x4.shared.b16 {%0,%1,%2,%3}, [%4];"
        : "=r"(r[0]), "=r"(r[1]), "=r"(r[2]), "=r"(r[3]) : "r"(addr));
}

// hi product: f16 inputs, f32 accumulate
__device__ __forceinline__ void mma16f(float c[4], const uint32_t a[4], uint32_t b0, uint32_t b1) {
    asm volatile(
        "mma.sync.aligned.m16n8k16.row.col.f32.f16.f16.f32 "
        "{%0,%1,%2,%3},{%4,%5,%6,%7},{%8,%9},{%0,%1,%2,%3};"
        : "+f"(c[0]), "+f"(c[1]), "+f"(c[2]), "+f"(c[3])
        : "r"(a[0]), "r"(a[1]), "r"(a[2]), "r"(a[3]), "r"(b0), "r"(b1));
}

// lo product: f16 inputs, f16 accumulate (testing double-rate legacy HMMA)
__device__ __forceinline__ void mma16h(uint32_t d[2], const uint32_t a[4], uint32_t b0, uint32_t b1) {
    asm volatile(
        "mma.sync.aligned.m16n8k16.row.col.f16.f16.f16.f16 "
        "{%0,%1},{%2,%3,%4,%5},{%6,%7},{%0,%1};"
        : "+r"(d[0]), "+r"(d[1])
        : "r"(a[0]), "r"(a[1]), "r"(a[2]), "r"(a[3]), "r"(b0), "r"(b1));
}

#define CP16(dst, src) \
    asm volatile("cp.async.cg.shared.global [%0], [%1], 16;" :: "r"(dst), "l"(src))
#define CP_COMMIT() asm volatile("cp.async.commit_group;" ::: "memory")
#define CP_WAIT1()  asm volatile("cp.async.wait_group 1;"  ::: "memory")

// B-image swizzle: rows are 64B (32 f16 k-values); mask stays below the row
// stride (bits 4-5 only), applied to the k-offset on both store and load.
__device__ __forceinline__ uint32_t bmask(int n) { return ((uint32_t)(n >> 1) & 3u) << 4; }

// ---------------------------------------------------------------------------
// Weight pre-convert: fp32 W[K,256] -> swizzled f16 hi + f16 lo*1024 image.
// One thread per packed uint32 slot; stores fully coalesced.
// ---------------------------------------------------------------------------
__global__ void __launch_bounds__(256)
convert_weights(const float* __restrict__ W1, const float* __restrict__ W2,
                const float* __restrict__ W3)
{
    int idx = blockIdx.x * 256 + threadIdx.x;    // 0 .. 81919 (hi uint32 slots)
    int chunk = idx >> 12;                       // 4096 slots per chunk
    int rem   = idx & 4095;
    int n     = rem >> 4;                        // 0..255
    int s     = rem & 15;                        // uint32 slot within 64B row

    const float* W; int kbase;
    if (chunk < 4)       { W = W1; kbase = chunk * 32; }
    else if (chunk < 12) { W = W2; kbase = (chunk - 4) * 32; }
    else                 { W = W3; kbase = (chunk - 12) * 32; }

    // inverse swizzle: stored byte = (k*2) ^ bm  =>  k*2 = (4s) ^ bm
    uint32_t bm = bmask(n);
    int k0 = (int)((((uint32_t)(4 * s)) ^ bm) >> 1);   // even; pair (k0, k0+1)
    float w0 = W[(kbase + k0) * 256 + n];
    float w1 = W[(kbase + k0 + 1) * 256 + n];

    __half h0 = __float2half_rn(w0);
    __half h1 = __float2half_rn(w1);
    __half l0 = __float2half_rn((w0 - __half2float(h0)) * LO_SCL);
    __half l1 = __float2half_rn((w1 - __half2float(h1)) * LO_SCL);

    uint32_t hi = ((uint32_t)*reinterpret_cast<uint16_t*>(&h1) << 16) |
                   (uint32_t)*reinterpret_cast<uint16_t*>(&h0);
    uint32_t lo = ((uint32_t)*reinterpret_cast<uint16_t*>(&l1) << 16) |
                   (uint32_t)*reinterpret_cast<uint16_t*>(&l0);

    uint8_t* cb = g_wimg + (size_t)chunk * CHUNK_BYTES;
    *(uint32_t*)(cb + n * 64 + 4 * s)            = hi;
    *(uint32_t*)(cb + CHUNK_HI + n * 64 + 4 * s) = lo;
}

// ---------------------------------------------------------------------------
// Encoder: persistent, TM=64 tiles, 3 fused layers. hi = f16*f16->f32 HMMA,
// lo = f16*f16->f16 HMMA (scaled x1024), folded at epilogue.
// R8-proven 2-slot ring: wait1 / barrier / mma / barrier / refill(g+2 mod 20).
// ---------------------------------------------------------------------------
__global__ void __launch_bounds__(THREADS, 1)
encoder_kernel(const float* __restrict__ x,
               const float* __restrict__ b1, const float* __restrict__ b2,
               const float* __restrict__ b3)
{
    extern __shared__ char smem[];
    const uint32_t sb = smem_u32(smem);
    const int tid  = threadIdx.x;
    const int lane = tid & 31;
    const int wid  = tid >> 5;
    const int wm   = wid >> 2;          // 0..1  (row half, 32 rows)
    const int wn   = wid & 3;           // 0..3  (col quarter, 64 cols)
    float* bias_s = (float*)(smem + SMEM_BIAS);
    float* red    = (float*)(smem + SMEM_RED);

    // --- prologue: prefetch chunks 0,1 ---
#pragma unroll
    for (int c0 = 0; c0 < 2; c0++) {
        const uint8_t* src = g_wimg + (size_t)c0 * CHUNK_BYTES;
        uint32_t dst = sb + SMEM_W + (uint32_t)c0 * CHUNK_BYTES;
#pragma unroll
        for (int i = 0; i < 8; i++)
            CP16(dst + (tid + i * 256) * 16, src + (tid + i * 256) * 16);
        CP_COMMIT();
    }

    // --- per-thread ldmatrix address precompute ---
    uint32_t a_base[2], a_xm[2];
    {
        int r0 = wm * 32 + (lane & 15);
#pragma unroll
        for (int mt = 0; mt < 2; mt++) {
            int r = r0 + mt * 16;
            a_base[mt] = sb + SMEM_A + (uint32_t)(r * 512);
            a_xm[mt]   = ((uint32_t)(r & 7)) << 4;
        }
    }
    const uint32_t a_h16 = (uint32_t)(lane >> 4) * 16;
    uint32_t b_off[4], b_xm[4];
    {
        int n0 = wn * 64 + (lane & 7) + ((lane >> 4) << 3);
#pragma unroll
        for (int q = 0; q < 4; q++) {
            int n = n0 + q * 16;
            b_off[q] = (uint32_t)(n * 64);
            b_xm[q]  = bmask(n);
        }
    }
    const uint32_t b_h16 = ((uint32_t)(lane >> 3) & 1) * 16;

    const float* biases[3] = { b1, b2, b3 };
    const int    ncs[3]    = { 4, 8, 8 };
    const int    gg = lane >> 2, t = lane & 3;

    for (int tile = blockIdx.x; tile < NTILES; tile += GRID_ENC) {
        // --- stage x tile [64 x 128] fp32 -> f16 into swizzled A (512B rows) ---
        {
            const float4* xt = (const float4*)(x + (size_t)tile * TM * NIN);
#pragma unroll
            for (int i = tid; i < TM * NIN / 4; i += THREADS) {
                float4 v = xt[i];
                int p = i * 4;
                int r = p >> 7, cc = p & 127;
                uint32_t off = ((uint32_t)(r * 512 + cc * 2)) ^ ((uint32_t)(r & 7) << 4);
                __half2 lo2 = __floats2half2_rn(v.x, v.y);
                __half2 hi2 = __floats2half2_rn(v.z, v.w);
                uint2 u;
                u.x = *reinterpret_cast<uint32_t*>(&lo2);
                u.y = *reinterpret_cast<uint32_t*>(&hi2);
                *(uint2*)(smem + SMEM_A + off) = u;
            }
        }
        __syncthreads();                 // x staged before layer-1 MMAs

        int g = 0;                       // within-tile chunk index (0..19)
        for (int L = 0; L < 3; L++) {
            bias_s[tid] = biases[L][tid];

            float    c [2][8][4];
            uint32_t cl[2][8][2];        // f16x2 accumulators for lo product
#pragma unroll
            for (int mt = 0; mt < 2; mt++)
#pragma unroll
                for (int nt = 0; nt < 8; nt++) {
#pragma unroll
                    for (int e = 0; e < 4; e++) c[mt][nt][e] = 0.f;
                    cl[mt][nt][0] = 0u; cl[mt][nt][1] = 0u;
                }

            const int nc = ncs[L];
            for (int lk = 0; lk < nc; lk++, g++) {
                CP_WAIT1();              // chunk g resident (1 pending: g+1)
                __syncthreads();

                const uint32_t wslot = sb + SMEM_W + (uint32_t)(g & 1) * CHUNK_BYTES;
#pragma unroll
                for (int ks = 0; ks < 2; ks++) {
                    uint32_t a[2][4];
                    const uint32_t kkA = (uint32_t)(lk * 64 + ks * 32) + a_h16;
#pragma unroll
                    for (int mt = 0; mt < 2; mt++)
                        ldsm4(a[mt], a_base[mt] + (kkA ^ a_xm[mt]));

                    const uint32_t kkB = (uint32_t)(ks * 32) + b_h16;
#pragma unroll
                    for (int q = 0; q < 4; q++) {
                        uint32_t bh[4], bl[4];
                        ldsm4(bh, wslot + b_off[q] + (kkB ^ b_xm[q]));
                        ldsm4(bl, wslot + CHUNK_HI + b_off[q] + (kkB ^ b_xm[q]));
                        const int nt0 = 2 * q;
#pragma unroll
                        for (int mt = 0; mt < 2; mt++) {
                            mma16f(c[mt][nt0],     a[mt], bh[0], bh[1]);
                            mma16f(c[mt][nt0 + 1], a[mt], bh[2], bh[3]);
                        }
#pragma unroll
                        for (int mt = 0; mt < 2; mt++) {
                            mma16h(cl[mt][nt0],     a[mt], bl[0], bl[1]);
                            mma16h(cl[mt][nt0 + 1], a[mt], bl[2], bl[3]);
                        }
                    }
                }

                __syncthreads();         // all warps done reading slot g&1
                {                        // refill with chunk (g+2) mod 20 (periodic stream)
                    int nxt = g + 2; if (nxt >= NCHUNKS) nxt -= NCHUNKS;
                    uint32_t dst = sb + SMEM_W + (uint32_t)(g & 1) * CHUNK_BYTES;
                    const uint8_t* src = g_wimg + (size_t)nxt * CHUNK_BYTES;
#pragma unroll
                    for (int i = 0; i < 8; i++)
                        CP16(dst + (tid + i * 256) * 16, src + (tid + i * 256) * 16);
                }
                CP_COMMIT();
            }

            if (L < 2) {
                // epilogue: fold lo (/1024), bias + relu -> f16 A, in place
#pragma unroll
                for (int mt = 0; mt < 2; mt++) {
                    const int r0 = wm * 32 + mt * 16 + gg;
                    const int r1 = r0 + 8;
                    const uint32_t x0 = ((uint32_t)(r0 & 7)) << 4;
                    const uint32_t x1 = ((uint32_t)(r1 & 7)) << 4;
#pragma unroll
                    for (int nt = 0; nt < 8; nt++) {
                        const int col = wn * 64 + nt * 8 + 2 * t;
                        const float bb0 = bias_s[col], bb1 = bias_s[col + 1];
                        float2 l01 = __half22float2(*reinterpret_cast<__half2*>(&cl[mt][nt][0]));
                        float2 l23 = __half22float2(*reinterpret_cast<__half2*>(&cl[mt][nt][1]));
                        float v0 = fmaxf(c[mt][nt][0] + LO_INV * l01.x + bb0, 0.f);
                        float v1 = fmaxf(c[mt][nt][1] + LO_INV * l01.y + bb1, 0.f);
                        float v2 = fmaxf(c[mt][nt][2] + LO_INV * l23.x + bb0, 0.f);
                        float v3 = fmaxf(c[mt][nt][3] + LO_INV * l23.y + bb1, 0.f);
                        __half2 p0 = __floats2half2_rn(v0, v1);
                        __half2 p1 = __floats2half2_rn(v2, v3);
                        uint32_t o0 = ((uint32_t)(r0 * 512 + col * 2)) ^ x0;
                        uint32_t o1 = ((uint32_t)(r1 * 512 + col * 2)) ^ x1;
                        *(uint32_t*)(smem + SMEM_A + o0) = *reinterpret_cast<uint32_t*>(&p0);
                        *(uint32_t*)(smem + SMEM_A + o1) = *reinterpret_cast<uint32_t*>(&p1);
                    }
                }
                __syncthreads();         // epilogue done before next layer's reads
            } else {
                // final: fold lo, bias + relu + column sums over this warp's 32 rows
#pragma unroll
                for (int nt = 0; nt < 8; nt++) {
                    const int col = wn * 64 + nt * 8 + 2 * t;
                    const float bb0 = bias_s[col], bb1 = bias_s[col + 1];
                    float s0 = 0.f, s1 = 0.f;
#pragma unroll
                    for (int mt = 0; mt < 2; mt++) {
                        float2 l01 = __half22float2(*reinterpret_cast<__half2*>(&cl[mt][nt][0]));
                        float2 l23 = __half22float2(*reinterpret_cast<__half2*>(&cl[mt][nt][1]));
                        s0 += fmaxf(c[mt][nt][0] + LO_INV * l01.x + bb0, 0.f)
                            + fmaxf(c[mt][nt][2] + LO_INV * l23.x + bb0, 0.f);
                        s1 += fmaxf(c[mt][nt][1] + LO_INV * l01.y + bb1, 0.f)
                            + fmaxf(c[mt][nt][3] + LO_INV * l23.y + bb1, 0.f);
                    }
#pragma unroll
                    for (int off = 16; off >= 4; off >>= 1) {
                        s0 += __shfl_down_sync(0xffffffffu, s0, off);
                        s1 += __shfl_down_sync(0xffffffffu, s1, off);
                    }
                    if (lane < 4) {      // lane == t; full 32-row sums for this warp
                        red[wm * 256 + col]     = s0;
                        red[wm * 256 + col + 1] = s1;
                    }
                }
                __syncthreads();
                g_partial[(size_t)tile * NHID + tid] = red[tid] + red[256 + tid];
                __syncthreads();         // red consumed before next tile reuses it
            }
        }
    }
}

// ---------------------------------------------------------------------------
// Fused decoder: mean->square->d1->d2->d3, one CTA per batch, 512 threads.
// All weight streams k-outer, coalesced row-major. Exact fp32.
// ---------------------------------------------------------------------------
__global__ void __launch_bounds__(512, 1)
decoder_kernel(const float* __restrict__ D1, const float* __restrict__ c1,
               const float* __restrict__ D2, const float* __restrict__ c2,
               const float* __restrict__ D3, const float* __restrict__ c3,
               float* __restrict__ out)
{
    __shared__ float p_s[NHID];
    __shared__ float d1_s[NDEC];
    __shared__ float d2_s[NDEC];
    __shared__ float wred[16 * NOUT];
    const int b = blockIdx.x, tid = threadIdx.x;
    const int lane = tid & 31, wrp = tid >> 5;

    if (tid < NHID) {
        const int tiles = NSET / TM;     // 64
        float s = 0.f;
        const float* base = g_partial + (size_t)(b * tiles) * NHID + tid;
#pragma unroll 8
        for (int i = 0; i < tiles; i++) s += base[(size_t)i * NHID];
        const float m = s * (1.0f / NSET);
        p_s[tid] = fmaxf(m * m, 0.f);
    }
    __syncthreads();

    {
        float acc = 0.f;
        const float* w = D1 + tid;
#pragma unroll 8
        for (int k = 0; k < NHID; k++) acc += p_s[k] * w[(size_t)k * NDEC];
        d1_s[tid] = fmaxf(acc + c1[tid], 0.f);
    }
    __syncthreads();

    {
        float acc = 0.f;
        const float* w = D2 + tid;
#pragma unroll 8
        for (int k = 0; k < NDEC; k++) acc += d1_s[k] * w[(size_t)k * NDEC];
        d2_s[tid] = fmaxf(acc + c2[tid], 0.f);
    }
    __syncthreads();

    {
        float part[NOUT];
        const float v = d2_s[tid];
        const float* w = D3 + (size_t)tid * NOUT;
#pragma unroll
        for (int o = 0; o < NOUT; o++) part[o] = v * w[o];
#pragma unroll
        for (int off = 16; off >= 1; off >>= 1)
#pragma unroll
            for (int o = 0; o < NOUT; o++)
                part[o] += __shfl_down_sync(0xffffffffu, part[o], off);
        if (lane == 0)
#pragma unroll
            for (int o = 0; o < NOUT; o++) wred[wrp * NOUT + o] = part[o];
    }
    __syncthreads();
    if (tid < NOUT) {
        float s = 0.f;
#pragma unroll
        for (int w = 0; w < 16; w++) s += wred[w * NOUT + tid];
        out[b * NOUT + tid] = c3[tid] + s;
    }
}

// ---------------------------------------------------------------------------
extern "C" void kernel_launch(void* const* d_in, const int* in_sizes, int n_in,
                              void* d_out, int out_size)
{
    (void)in_sizes; (void)n_in; (void)out_size;
    const float* x  = (const float*)d_in[0];
    const float* W1 = (const float*)d_in[1];
    const float* b1 = (const float*)d_in[2];
    const float* W2 = (const float*)d_in[3];
    const float* b2 = (const float*)d_in[4];
    const float* W3 = (const float*)d_in[5];
    const float* b3 = (const float*)d_in[6];
    const float* D1 = (const float*)d_in[7];
    const float* c1 = (const float*)d_in[8];
    const float* D2 = (const float*)d_in[9];
    const float* c2 = (const float*)d_in[10];
    const float* D3 = (const float*)d_in[11];
    const float* c3 = (const float*)d_in[12];

    cudaFuncSetAttribute(encoder_kernel, cudaFuncAttributeMaxDynamicSharedMemorySize, SMEM_TOTAL);

    convert_weights<<<320, 256>>>(W1, W2, W3);
    encoder_kernel<<<GRID_ENC, THREADS, SMEM_TOTAL>>>(x, b1, b2, b3);
    decoder_kernel<<<BATCH, 512>>>(D1, c1, D2, c2, D3, c3, (float*)d_out);
}

// round 12
// speedup vs baseline: 1.8624x; 1.7361x over previous
#include <cuda_runtime.h>
#include <cuda_fp16.h>
#include <cstdint>

// ---------------------------------------------------------------------------
// Problem dims
// ---------------------------------------------------------------------------
#define NIN   128
#define NHID  256
#define NDEC  512
#define NOUT  10
#define BATCH 32
#define NSET  4096

#define TM       64                     // rows per tile
#define NTILES   (BATCH * NSET / TM)    // 2048
#define THREADS  256                    // 8 warps: 2 (row halves of 32) x 4 (col quarters)
#define GRID_ENC 296                    // persistent: 2 CTAs per SM

// Weight image: k-chunks of 64, f16 single precision product. chunk = 32KB.
#define CHUNK_BYTES 32768
#define NCHUNKS     10                  // L1:2  L2:4  L3:4  (contiguous)
#define IMG_BYTES   (NCHUNKS * CHUNK_BYTES)

// SMEM layout (bytes) — total 101376 => 2 CTAs/SM
#define SMEM_A     0                    // 64 rows x 512B f16, XOR-swizzled
#define SMEM_W     32768                // 2 slots x 32KB ring
#define SMEM_BIAS  98304                // 256 floats
#define SMEM_RED   99328                // 2 x 256 floats
#define SMEM_TOTAL 101376

// ---------------------------------------------------------------------------
// Device globals (static; fully rewritten every launch)
// ---------------------------------------------------------------------------
__device__ __align__(128) uint8_t g_wimg[IMG_BYTES];
__device__ float g_partial[NTILES * NHID];

// ---------------------------------------------------------------------------
// PTX helpers (baseline sm_80-era PTX only: safe at compute_103 target)
// ---------------------------------------------------------------------------
__device__ __forceinline__ uint32_t smem_u32(const void* p) {
    uint32_t a;
    asm("{ .reg .u64 t; cvta.to.shared.u64 t, %1; cvt.u32.u64 %0, t; }" : "=r"(a) : "l"(p));
    return a;
}

__device__ __forceinline__ void ldsm4(uint32_t r[4], uint32_t addr) {
    asm volatile("ldmatrix.sync.aligned.m8n8.x4.shared.b16 {%0,%1,%2,%3}, [%4];"
        : "=r"(r[0]), "=r"(r[1]), "=r"(r[2]), "=r"(r[3]) : "r"(addr));
}

// f16 inputs, f32 accumulate
__device__ __forceinline__ void mma16f(float c[4], const uint32_t a[4], uint32_t b0, uint32_t b1) {
    asm volatile(
        "mma.sync.aligned.m16n8k16.row.col.f32.f16.f16.f32 "
        "{%0,%1,%2,%3},{%4,%5,%6,%7},{%8,%9},{%0,%1,%2,%3};"
        : "+f"(c[0]), "+f"(c[1]), "+f"(c[2]), "+f"(c[3])
        : "r"(a[0]), "r"(a[1]), "r"(a[2]), "r"(a[3]), "r"(b0), "r"(b1));
}

#define CP16(dst, src) \
    asm volatile("cp.async.cg.shared.global [%0], [%1], 16;" :: "r"(dst), "l"(src))
#define CP_COMMIT() asm volatile("cp.async.commit_group;" ::: "memory")
#define CP_WAIT1()  asm volatile("cp.async.wait_group 1;"  ::: "memory")

// B-image swizzle: rows are 128B (64 f16 k-values); 3-bit mask on bits 4-6,
// strictly below the 128B row stride; applied to the k-offset on store AND load.
__device__ __forceinline__ uint32_t bmask(int n) { return ((uint32_t)n & 7u) << 4; }

// ---------------------------------------------------------------------------
// Weight pre-convert: fp32 W[K,256] -> swizzled f16 image (k64 chunks).
// One thread per packed uint32 slot; stores fully coalesced.
// ---------------------------------------------------------------------------
__global__ void __launch_bounds__(256)
convert_weights(const float* __restrict__ W1, const float* __restrict__ W2,
                const float* __restrict__ W3)
{
    int idx = blockIdx.x * 256 + threadIdx.x;    // 0 .. 81919 (uint32 slots)
    int chunk = idx >> 13;                       // 8192 slots per chunk
    int rem   = idx & 8191;
    int n     = rem >> 5;                        // 0..255
    int s     = rem & 31;                        // uint32 slot within 128B row

    const float* W; int kbase;
    if (chunk < 2)      { W = W1; kbase = chunk * 64; }
    else if (chunk < 6) { W = W2; kbase = (chunk - 2) * 64; }
    else                { W = W3; kbase = (chunk - 6) * 64; }

    // inverse swizzle: stored byte = (k*2) ^ bm  =>  k*2 = (4s) ^ bm
    uint32_t bm = bmask(n);
    int k0 = (int)((((uint32_t)(4 * s)) ^ bm) >> 1);   // even; pair (k0, k0+1)
    float w0 = W[(kbase + k0) * 256 + n];
    float w1 = W[(kbase + k0 + 1) * 256 + n];

    __half h0 = __float2half_rn(w0);
    __half h1 = __float2half_rn(w1);
    uint32_t hi = ((uint32_t)*reinterpret_cast<uint16_t*>(&h1) << 16) |
                   (uint32_t)*reinterpret_cast<uint16_t*>(&h0);

    *(uint32_t*)(g_wimg + (size_t)chunk * CHUNK_BYTES + n * 128 + 4 * s) = hi;
}

// ---------------------------------------------------------------------------
// Encoder: persistent, 2 CTAs/SM, TM=64 tiles, 3 fused layers. Single f16
// HMMA product per k-step. R8-proven 2-slot ring with k64 chunks (10/tile).
// ---------------------------------------------------------------------------
__global__ void __launch_bounds__(THREADS, 2)
encoder_kernel(const float* __restrict__ x,
               const float* __restrict__ b1, const float* __restrict__ b2,
               const float* __restrict__ b3)
{
    extern __shared__ char smem[];
    const uint32_t sb = smem_u32(smem);
    const int tid  = threadIdx.x;
    const int lane = tid & 31;
    const int wid  = tid >> 5;
    const int wm   = wid >> 2;          // 0..1  (row half, 32 rows)
    const int wn   = wid & 3;           // 0..3  (col quarter, 64 cols)
    float* bias_s = (float*)(smem + SMEM_BIAS);
    float* red    = (float*)(smem + SMEM_RED);

    // --- prologue: prefetch chunks 0,1 ---
#pragma unroll
    for (int c0 = 0; c0 < 2; c0++) {
        const uint8_t* src = g_wimg + (size_t)c0 * CHUNK_BYTES;
        uint32_t dst = sb + SMEM_W + (uint32_t)c0 * CHUNK_BYTES;
#pragma unroll
        for (int i = 0; i < 8; i++)
            CP16(dst + (tid + i * 256) * 16, src + (tid + i * 256) * 16);
        CP_COMMIT();
    }

    // --- per-thread ldmatrix address precompute ---
    uint32_t a_base[2], a_xm[2];
    {
        int r0 = wm * 32 + (lane & 15);
#pragma unroll
        for (int mt = 0; mt < 2; mt++) {
            int r = r0 + mt * 16;
            a_base[mt] = sb + SMEM_A + (uint32_t)(r * 512);
            a_xm[mt]   = ((uint32_t)(r & 7)) << 4;
        }
    }
    const uint32_t a_h16 = (uint32_t)(lane >> 4) * 16;
    uint32_t b_off[4], b_xm[4];
    {
        int n0 = wn * 64 + (lane & 7) + ((lane >> 4) << 3);
#pragma unroll
        for (int q = 0; q < 4; q++) {
            int n = n0 + q * 16;
            b_off[q] = (uint32_t)(n * 128);
            b_xm[q]  = bmask(n);
        }
    }
    const uint32_t b_h16 = ((uint32_t)(lane >> 3) & 1) * 16;

    const float* biases[3] = { b1, b2, b3 };
    const int    ncs[3]    = { 2, 4, 4 };
    const int    gg = lane >> 2, t = lane & 3;

    for (int tile = blockIdx.x; tile < NTILES; tile += GRID_ENC) {
        // --- stage x tile [64 x 128] fp32 -> f16 into swizzled A (512B rows) ---
        {
            const float4* xt = (const float4*)(x + (size_t)tile * TM * NIN);
#pragma unroll
            for (int i = tid; i < TM * NIN / 4; i += THREADS) {
                float4 v = xt[i];
                int p = i * 4;
                int r = p >> 7, cc = p & 127;
                uint32_t off = ((uint32_t)(r * 512 + cc * 2)) ^ ((uint32_t)(r & 7) << 4);
                __half2 lo2 = __floats2half2_rn(v.x, v.y);
                __half2 hi2 = __floats2half2_rn(v.z, v.w);
                uint2 u;
                u.x = *reinterpret_cast<uint32_t*>(&lo2);
                u.y = *reinterpret_cast<uint32_t*>(&hi2);
                *(uint2*)(smem + SMEM_A + off) = u;
            }
        }
        __syncthreads();                 // x staged before layer-1 MMAs

        int g = 0;                       // within-tile chunk index (0..9)
        for (int L = 0; L < 3; L++) {
            bias_s[tid] = biases[L][tid];

            float c[2][8][4];
#pragma unroll
            for (int mt = 0; mt < 2; mt++)
#pragma unroll
                for (int nt = 0; nt < 8; nt++)
#pragma unroll
                    for (int e = 0; e < 4; e++) c[mt][nt][e] = 0.f;

            const int nc = ncs[L];
            for (int lk = 0; lk < nc; lk++, g++) {
                CP_WAIT1();              // chunk g resident (1 pending: g+1)
                __syncthreads();

                const uint32_t wslot = sb + SMEM_W + (uint32_t)(g & 1) * CHUNK_BYTES;
#pragma unroll
                for (int ks = 0; ks < 4; ks++) {     // k64 chunk = 4 k16 steps
                    uint32_t a[2][4];
                    const uint32_t kkA = (uint32_t)(lk * 128 + ks * 32) + a_h16;
#pragma unroll
                    for (int mt = 0; mt < 2; mt++)
                        ldsm4(a[mt], a_base[mt] + (kkA ^ a_xm[mt]));

                    const uint32_t kkB = (uint32_t)(ks * 32) + b_h16;
#pragma unroll
                    for (int q = 0; q < 4; q++) {
                        uint32_t bh[4];
                        ldsm4(bh, wslot + b_off[q] + (kkB ^ b_xm[q]));
                        const int nt0 = 2 * q;
#pragma unroll
                        for (int mt = 0; mt < 2; mt++) {
                            mma16f(c[mt][nt0],     a[mt], bh[0], bh[1]);
                            mma16f(c[mt][nt0 + 1], a[mt], bh[2], bh[3]);
                        }
                    }
                }

                __syncthreads();         // all warps done reading slot g&1
                {                        // refill with chunk (g+2) mod 10 (periodic stream)
                    int nxt = g + 2; if (nxt >= NCHUNKS) nxt -= NCHUNKS;
                    uint32_t dst = sb + SMEM_W + (uint32_t)(g & 1) * CHUNK_BYTES;
                    const uint8_t* src = g_wimg + (size_t)nxt * CHUNK_BYTES;
#pragma unroll
                    for (int i = 0; i < 8; i++)
                        CP16(dst + (tid + i * 256) * 16, src + (tid + i * 256) * 16);
                }
                CP_COMMIT();
            }

            if (L < 2) {
                // epilogue: bias + relu -> f16, rewrite A in place
#pragma unroll
                for (int mt = 0; mt < 2; mt++) {
                    const int r0 = wm * 32 + mt * 16 + gg;
                    const int r1 = r0 + 8;
                    const uint32_t x0 = ((uint32_t)(r0 & 7)) << 4;
                    const uint32_t x1 = ((uint32_t)(r1 & 7)) << 4;
#pragma unroll
                    for (int nt = 0; nt < 8; nt++) {
                        const int col = wn * 64 + nt * 8 + 2 * t;
                        const float bb0 = bias_s[col], bb1 = bias_s[col + 1];
                        __half2 p0 = __floats2half2_rn(
                            fmaxf(c[mt][nt][0] + bb0, 0.f), fmaxf(c[mt][nt][1] + bb1, 0.f));
                        __half2 p1 = __floats2half2_rn(
                            fmaxf(c[mt][nt][2] + bb0, 0.f), fmaxf(c[mt][nt][3] + bb1, 0.f));
                        uint32_t o0 = ((uint32_t)(r0 * 512 + col * 2)) ^ x0;
                        uint32_t o1 = ((uint32_t)(r1 * 512 + col * 2)) ^ x1;
                        *(uint32_t*)(smem + SMEM_A + o0) = *reinterpret_cast<uint32_t*>(&p0);
                        *(uint32_t*)(smem + SMEM_A + o1) = *reinterpret_cast<uint32_t*>(&p1);
                    }
                }
                __syncthreads();         // epilogue done before next layer's reads
            } else {
                // final: bias + relu + column sums over this warp's 32 rows
#pragma unroll
                for (int nt = 0; nt < 8; nt++) {
                    const int col = wn * 64 + nt * 8 + 2 * t;
                    const float bb0 = bias_s[col], bb1 = bias_s[col + 1];
                    float s0 = 0.f, s1 = 0.f;
#pragma unroll
                    for (int mt = 0; mt < 2; mt++) {
                        s0 += fmaxf(c[mt][nt][0] + bb0, 0.f) + fmaxf(c[mt][nt][2] + bb0, 0.f);
                        s1 += fmaxf(c[mt][nt][1] + bb1, 0.f) + fmaxf(c[mt][nt][3] + bb1, 0.f);
                    }
#pragma unroll
                    for (int off = 16; off >= 4; off >>= 1) {
                        s0 += __shfl_down_sync(0xffffffffu, s0, off);
                        s1 += __shfl_down_sync(0xffffffffu, s1, off);
                    }
                    if (lane < 4) {      // lane == t; full 32-row sums for this warp
                        red[wm * 256 + col]     = s0;
                        red[wm * 256 + col + 1] = s1;
                    }
                }
                __syncthreads();
                g_partial[(size_t)tile * NHID + tid] = red[tid] + red[256 + tid];
                __syncthreads();         // red consumed before next tile reuses it
            }
        }
    }
}

// ---------------------------------------------------------------------------
// Fused decoder: mean->square->d1->d2->d3, one CTA per batch, 512 threads.
// All weight streams k-outer, coalesced row-major. Exact fp32.
// ---------------------------------------------------------------------------
__global__ void __launch_bounds__(512, 1)
decoder_kernel(const float* __restrict__ D1, const float* __restrict__ c1,
               const float* __restrict__ D2, const float* __restrict__ c2,
               const float* __restrict__ D3, const float* __restrict__ c3,
               float* __restrict__ out)
{
    __shared__ float p_s[NHID];
    __shared__ float d1_s[NDEC];
    __shared__ float d2_s[NDEC];
    __shared__ float wred[16 * NOUT];
    const int b = blockIdx.x, tid = threadIdx.x;
    const int lane = tid & 31, wrp = tid >> 5;

    if (tid < NHID) {
        const int tiles = NSET / TM;     // 64
        float s = 0.f;
        const float* base = g_partial + (size_t)(b * tiles) * NHID + tid;
#pragma unroll 8
        for (int i = 0; i < tiles; i++) s += base[(size_t)i * NHID];
        const float m = s * (1.0f / NSET);
        p_s[tid] = fmaxf(m * m, 0.f);
    }
    __syncthreads();

    {
        float acc = 0.f;
        const float* w = D1 + tid;
#pragma unroll 8
        for (int k = 0; k < NHID; k++) acc += p_s[k] * w[(size_t)k * NDEC];
        d1_s[tid] = fmaxf(acc + c1[tid], 0.f);
    }
    __syncthreads();

    {
        float acc = 0.f;
        const float* w = D2 + tid;
#pragma unroll 8
        for (int k = 0; k < NDEC; k++) acc += d1_s[k] * w[(size_t)k * NDEC];
        d2_s[tid] = fmaxf(acc + c2[tid], 0.f);
    }
    __syncthreads();

    {
        float part[NOUT];
        const float v = d2_s[tid];
        const float* w = D3 + (size_t)tid * NOUT;
#pragma unroll
        for (int o = 0; o < NOUT; o++) part[o] = v * w[o];
#pragma unroll
        for (int off = 16; off >= 1; off >>= 1)
#pragma unroll
            for (int o = 0; o < NOUT; o++)
                part[o] += __shfl_down_sync(0xffffffffu, part[o], off);
        if (lane == 0)
#pragma unroll
            for (int o = 0; o < NOUT; o++) wred[wrp * NOUT + o] = part[o];
    }
    __syncthreads();
    if (tid < NOUT) {
        float s = 0.f;
#pragma unroll
        for (int w = 0; w < 16; w++) s += wred[w * NOUT + tid];
        out[b * NOUT + tid] = c3[tid] + s;
    }
}

// ---------------------------------------------------------------------------
extern "C" void kernel_launch(void* const* d_in, const int* in_sizes, int n_in,
                              void* d_out, int out_size)
{
    (void)in_sizes; (void)n_in; (void)out_size;
    const float* x  = (const float*)d_in[0];
    const float* W1 = (const float*)d_in[1];
    const float* b1 = (const float*)d_in[2];
    const float* W2 = (const float*)d_in[3];
    const float* b2 = (const float*)d_in[4];
    const float* W3 = (const float*)d_in[5];
    const float* b3 = (const float*)d_in[6];
    const float* D1 = (const float*)d_in[7];
    const float* c1 = (const float*)d_in[8];
    const float* D2 = (const float*)d_in[9];
    const float* c2 = (const float*)d_in[10];
    const float* D3 = (const float*)d_in[11];
    const float* c3 = (const float*)d_in[12];

    cudaFuncSetAttribute(encoder_kernel, cudaFuncAttributeMaxDynamicSharedMemorySize, SMEM_TOTAL);

    convert_weights<<<320, 256>>>(W1, W2, W3);
    encoder_kernel<<<GRID_ENC, THREADS, SMEM_TOTAL>>>(x, b1, b2, b3);
    decoder_kernel<<<BATCH, 512>>>(D1, c1, D2, c2, D3, c3, (float*)d_out);
}

// round 13
// speedup vs baseline: 1.9290x; 1.0358x over previous
#include <cuda_runtime.h>
#include <cuda_fp16.h>
#include <cstdint>

// ---------------------------------------------------------------------------
// Problem dims
// ---------------------------------------------------------------------------
#define NIN   128
#define NHID  256
#define NDEC  512
#define NOUT  10
#define BATCH 32
#define NSET  4096

#define TM       64                     // rows per tile
#define NTILES   (BATCH * NSET / TM)    // 2048
#define THREADS  256                    // 8 warps: 2 (row halves of 32) x 4 (col quarters)
#define GRID_ENC 296                    // persistent: 2 CTAs per SM

// Weight image: k-chunks of 64, f16 single product. chunk = 32KB.
#define CHUNK_BYTES 32768
#define NCHUNKS     10                  // L1:2  L2:4  L3:4  (contiguous)
#define IMG_BYTES   (NCHUNKS * CHUNK_BYTES)

// SMEM layout (bytes) — total 101376 => 2 CTAs/SM
#define SMEM_A     0                    // 64 rows x 512B f16, XOR-swizzled
#define SMEM_W     32768                // 2 slots x 32KB ring
#define SMEM_BIAS  98304                // 3 x 256 floats (all layers, loaded once)
#define SMEM_TOTAL 101376

// ---------------------------------------------------------------------------
// Device globals (static; fully rewritten every launch)
// ---------------------------------------------------------------------------
__device__ __align__(128) uint8_t g_wimg[IMG_BYTES];
__device__ float g_partial[NTILES * 2 * NHID];   // per tile: [half0 256 | half1 256]

// ---------------------------------------------------------------------------
// PTX helpers (baseline sm_80-era PTX only: safe at compute_103 target)
// ---------------------------------------------------------------------------
__device__ __forceinline__ uint32_t smem_u32(const void* p) {
    uint32_t a;
    asm("{ .reg .u64 t; cvta.to.shared.u64 t, %1; cvt.u32.u64 %0, t; }" : "=r"(a) : "l"(p));
    return a;
}

__device__ __forceinline__ void ldsm4(uint32_t r[4], uint32_t addr) {
    asm volatile("ldmatrix.sync.aligned.m8n8.x4.shared.b16 {%0,%1,%2,%3}, [%4];"
        : "=r"(r[0]), "=r"(r[1]), "=r"(r[2]), "=r"(r[3]) : "r"(addr));
}

// f16 inputs, f32 accumulate
__device__ __forceinline__ void mma16f(float c[4], const uint32_t a[4], uint32_t b0, uint32_t b1) {
    asm volatile(
        "mma.sync.aligned.m16n8k16.row.col.f32.f16.f16.f32 "
        "{%0,%1,%2,%3},{%4,%5,%6,%7},{%8,%9},{%0,%1,%2,%3};"
        : "+f"(c[0]), "+f"(c[1]), "+f"(c[2]), "+f"(c[3])
        : "r"(a[0]), "r"(a[1]), "r"(a[2]), "r"(a[3]), "r"(b0), "r"(b1));
}

#define CP16(dst, src) \
    asm volatile("cp.async.cg.shared.global [%0], [%1], 16;" :: "r"(dst), "l"(src))
#define CP_COMMIT() asm volatile("cp.async.commit_group;" ::: "memory")
#define CP_WAIT1()  asm volatile("cp.async.wait_group 1;"  ::: "memory")

// B-image swizzle: rows are 128B (64 f16 k-values); 3-bit mask on bits 4-6,
// strictly below the 128B row stride; applied to the k-offset on store AND load.
__device__ __forceinline__ uint32_t bmask(int n) { return ((uint32_t)n & 7u) << 4; }

// ---------------------------------------------------------------------------
// Weight pre-convert: fp32 W[K,256] -> swizzled f16 image (k64 chunks).
// ---------------------------------------------------------------------------
__global__ void __launch_bounds__(256)
convert_weights(const float* __restrict__ W1, const float* __restrict__ W2,
                const float* __restrict__ W3)
{
    int idx = blockIdx.x * 256 + threadIdx.x;    // 0 .. 81919 (uint32 slots)
    int chunk = idx >> 13;                       // 8192 slots per chunk
    int rem   = idx & 8191;
    int n     = rem >> 5;                        // 0..255
    int s     = rem & 31;                        // uint32 slot within 128B row

    const float* W; int kbase;
    if (chunk < 2)      { W = W1; kbase = chunk * 64; }
    else if (chunk < 6) { W = W2; kbase = (chunk - 2) * 64; }
    else                { W = W3; kbase = (chunk - 6) * 64; }

    // inverse swizzle: stored byte = (k*2) ^ bm  =>  k*2 = (4s) ^ bm
    uint32_t bm = bmask(n);
    int k0 = (int)((((uint32_t)(4 * s)) ^ bm) >> 1);   // even; pair (k0, k0+1)
    float w0 = W[(kbase + k0) * 256 + n];
    float w1 = W[(kbase + k0 + 1) * 256 + n];

    __half h0 = __float2half_rn(w0);
    __half h1 = __float2half_rn(w1);
    uint32_t hi = ((uint32_t)*reinterpret_cast<uint16_t*>(&h1) << 16) |
                   (uint32_t)*reinterpret_cast<uint16_t*>(&h0);

    *(uint32_t*)(g_wimg + (size_t)chunk * CHUNK_BYTES + n * 128 + 4 * s) = hi;
}

// ---------------------------------------------------------------------------
// Encoder: persistent, 2 CTAs/SM, TM=64 tiles, 3 fused layers, single f16
// product. 2-slot k64 ring; biases preloaded once; final-layer partial sums
// go straight to global per warp-half (no smem reduce, no extra barriers).
// ---------------------------------------------------------------------------
__global__ void __launch_bounds__(THREADS, 2)
encoder_kernel(const float* __restrict__ x,
               const float* __restrict__ b1, const float* __restrict__ b2,
               const float* __restrict__ b3)
{
    extern __shared__ char smem[];
    const uint32_t sb = smem_u32(smem);
    const int tid  = threadIdx.x;
    const int lane = tid & 31;
    const int wid  = tid >> 5;
    const int wm   = wid >> 2;          // 0..1  (row half, 32 rows)
    const int wn   = wid & 3;           // 0..3  (col quarter, 64 cols)
    float* bias_s = (float*)(smem + SMEM_BIAS);   // [3][256]

    // --- prologue: prefetch chunks 0,1 ---
#pragma unroll
    for (int c0 = 0; c0 < 2; c0++) {
        const uint8_t* src = g_wimg + (size_t)c0 * CHUNK_BYTES;
        uint32_t dst = sb + SMEM_W + (uint32_t)c0 * CHUNK_BYTES;
#pragma unroll
        for (int i = 0; i < 8; i++)
            CP16(dst + (tid + i * 256) * 16, src + (tid + i * 256) * 16);
        CP_COMMIT();
    }

    // --- preload all 3 biases once ---
    bias_s[tid]       = b1[tid];
    bias_s[256 + tid] = b2[tid];
    bias_s[512 + tid] = b3[tid];

    // --- per-thread ldmatrix address precompute ---
    uint32_t a_base[2], a_xm[2];
    {
        int r0 = wm * 32 + (lane & 15);
#pragma unroll
        for (int mt = 0; mt < 2; mt++) {
            int r = r0 + mt * 16;
            a_base[mt] = sb + SMEM_A + (uint32_t)(r * 512);
            a_xm[mt]   = ((uint32_t)(r & 7)) << 4;
        }
    }
    const uint32_t a_h16 = (uint32_t)(lane >> 4) * 16;
    uint32_t b_off[4], b_xm[4];
    {
        int n0 = wn * 64 + (lane & 7) + ((lane >> 4) << 3);
#pragma unroll
        for (int q = 0; q < 4; q++) {
            int n = n0 + q * 16;
            b_off[q] = (uint32_t)(n * 128);
            b_xm[q]  = bmask(n);
        }
    }
    const uint32_t b_h16 = ((uint32_t)(lane >> 3) & 1) * 16;

    const int ncs[3] = { 2, 4, 4 };
    const int gg = lane >> 2, t = lane & 3;

    for (int tile = blockIdx.x; tile < NTILES; tile += GRID_ENC) {
        // --- stage x tile [64 x 128] fp32 -> f16 into swizzled A (512B rows) ---
        // (safe: last tile's final post-MMA barrier ordered all A reads)
        {
            const float4* xt = (const float4*)(x + (size_t)tile * TM * NIN);
#pragma unroll
            for (int i = tid; i < TM * NIN / 4; i += THREADS) {
                float4 v = xt[i];
                int p = i * 4;
                int r = p >> 7, cc = p & 127;
                uint32_t off = ((uint32_t)(r * 512 + cc * 2)) ^ ((uint32_t)(r & 7) << 4);
                __half2 lo2 = __floats2half2_rn(v.x, v.y);
                __half2 hi2 = __floats2half2_rn(v.z, v.w);
                uint2 u;
                u.x = *reinterpret_cast<uint32_t*>(&lo2);
                u.y = *reinterpret_cast<uint32_t*>(&hi2);
                *(uint2*)(smem + SMEM_A + off) = u;
            }
        }
        __syncthreads();                 // x staged (also covers bias preload on tile 0)

        int g = 0;                       // within-tile chunk index (0..9)
        for (int L = 0; L < 3; L++) {
            const float* bl_s = bias_s + L * 256;

            float c[2][8][4];
#pragma unroll
            for (int mt = 0; mt < 2; mt++)
#pragma unroll
                for (int nt = 0; nt < 8; nt++)
#pragma unroll
                    for (int e = 0; e < 4; e++) c[mt][nt][e] = 0.f;

            const int nc = ncs[L];
            for (int lk = 0; lk < nc; lk++, g++) {
                CP_WAIT1();              // chunk g resident (1 pending: g+1)
                __syncthreads();         // (also orders prev epilogue's A writes)

                const uint32_t wslot = sb + SMEM_W + (uint32_t)(g & 1) * CHUNK_BYTES;
#pragma unroll
                for (int ks = 0; ks < 4; ks++) {     // k64 chunk = 4 k16 steps
                    uint32_t a[2][4];
                    const uint32_t kkA = (uint32_t)(lk * 128 + ks * 32) + a_h16;
#pragma unroll
                    for (int mt = 0; mt < 2; mt++)
                        ldsm4(a[mt], a_base[mt] + (kkA ^ a_xm[mt]));

                    const uint32_t kkB = (uint32_t)(ks * 32) + b_h16;
#pragma unroll
                    for (int q = 0; q < 4; q++) {
                        uint32_t bh[4];
                        ldsm4(bh, wslot + b_off[q] + (kkB ^ b_xm[q]));
                        const int nt0 = 2 * q;
#pragma unroll
                        for (int mt = 0; mt < 2; mt++) {
                            mma16f(c[mt][nt0],     a[mt], bh[0], bh[1]);
                            mma16f(c[mt][nt0 + 1], a[mt], bh[2], bh[3]);
                        }
                    }
                }

                __syncthreads();         // all warps done reading slot g&1
                {                        // refill with chunk (g+2) mod 10 (periodic stream)
                    int nxt = g + 2; if (nxt >= NCHUNKS) nxt -= NCHUNKS;
                    uint32_t dst = sb + SMEM_W + (uint32_t)(g & 1) * CHUNK_BYTES;
                    const uint8_t* src = g_wimg + (size_t)nxt * CHUNK_BYTES;
#pragma unroll
                    for (int i = 0; i < 8; i++)
                        CP16(dst + (tid + i * 256) * 16, src + (tid + i * 256) * 16);
                }
                CP_COMMIT();
            }

            if (L < 2) {
                // epilogue: bias + relu -> f16, rewrite A in place.
                // Ordering vs next layer's MMA reads: next chunk-top __syncthreads.
#pragma unroll
                for (int mt = 0; mt < 2; mt++) {
                    const int r0 = wm * 32 + mt * 16 + gg;
                    const int r1 = r0 + 8;
                    const uint32_t x0 = ((uint32_t)(r0 & 7)) << 4;
                    const uint32_t x1 = ((uint32_t)(r1 & 7)) << 4;
#pragma unroll
                    for (int nt = 0; nt < 8; nt++) {
                        const int col = wn * 64 + nt * 8 + 2 * t;
                        const float bb0 = bl_s[col], bb1 = bl_s[col + 1];
                        __half2 p0 = __floats2half2_rn(
                            fmaxf(c[mt][nt][0] + bb0, 0.f), fmaxf(c[mt][nt][1] + bb1, 0.f));
                        __half2 p1 = __floats2half2_rn(
                            fmaxf(c[mt][nt][2] + bb0, 0.f), fmaxf(c[mt][nt][3] + bb1, 0.f));
                        uint32_t o0 = ((uint32_t)(r0 * 512 + col * 2)) ^ x0;
                        uint32_t o1 = ((uint32_t)(r1 * 512 + col * 2)) ^ x1;
                        *(uint32_t*)(smem + SMEM_A + o0) = *reinterpret_cast<uint32_t*>(&p0);
                        *(uint32_t*)(smem + SMEM_A + o1) = *reinterpret_cast<uint32_t*>(&p1);
                    }
                }
            } else {
                // final: bias + relu + 32-row column sums, straight to global
                // per warp-half (no smem reduce, no barriers; A untouched).
                float* gout = g_partial + (size_t)tile * 2 * NHID + wm * NHID;
#pragma unroll
                for (int nt = 0; nt < 8; nt++) {
                    const int col = wn * 64 + nt * 8 + 2 * t;
                    const float bb0 = bl_s[col], bb1 = bl_s[col + 1];
                    float s0 = 0.f, s1 = 0.f;
#pragma unroll
                    for (int mt = 0; mt < 2; mt++) {
                        s0 += fmaxf(c[mt][nt][0] + bb0, 0.f) + fmaxf(c[mt][nt][2] + bb0, 0.f);
                        s1 += fmaxf(c[mt][nt][1] + bb1, 0.f) + fmaxf(c[mt][nt][3] + bb1, 0.f);
                    }
#pragma unroll
                    for (int off = 16; off >= 4; off >>= 1) {
                        s0 += __shfl_down_sync(0xffffffffu, s0, off);
                        s1 += __shfl_down_sync(0xffffffffu, s1, off);
                    }
                    if (lane < 4) {      // lane == t; full 32-row sums for this warp
                        float2 v2 = make_float2(s0, s1);
                        *(float2*)(gout + col) = v2;
                    }
                }
            }
        }
    }
}

// ---------------------------------------------------------------------------
// Fused decoder: mean->square->d1->d2->d3, one CTA per batch, 512 threads.
// All weight streams k-outer, coalesced row-major. Exact fp32.
// ---------------------------------------------------------------------------
__global__ void __launch_bounds__(512, 1)
decoder_kernel(const float* __restrict__ D1, const float* __restrict__ c1,
               const float* __restrict__ D2, const float* __restrict__ c2,
               const float* __restrict__ D3, const float* __restrict__ c3,
               float* __restrict__ out)
{
    __shared__ float p_s[NHID];
    __shared__ float d1_s[NDEC];
    __shared__ float d2_s[NDEC];
    __shared__ float wred[16 * NOUT];
    const int b = blockIdx.x, tid = threadIdx.x;
    const int lane = tid & 31, wrp = tid >> 5;

    // mean over 64 tiles x 2 halves (deterministic fixed order), p = relu(m*m)
    if (tid < NHID) {
        const int tiles = NSET / TM;     // 64
        float s = 0.f;
        const float* base = g_partial + (size_t)(b * tiles) * 2 * NHID + tid;
#pragma unroll 8
        for (int i = 0; i < 2 * tiles; i++) s += base[(size_t)i * NHID];
        const float m = s * (1.0f / NSET);
        p_s[tid] = fmaxf(m * m, 0.f);
    }
    __syncthreads();

    {
        float acc = 0.f;
        const float* w = D1 + tid;
#pragma unroll 8
        for (int k = 0; k < NHID; k++) acc += p_s[k] * w[(size_t)k * NDEC];
        d1_s[tid] = fmaxf(acc + c1[tid], 0.f);
    }
    __syncthreads();

    {
        float acc = 0.f;
        const float* w = D2 + tid;
#pragma unroll 8
        for (int k = 0; k < NDEC; k++) acc += d1_s[k] * w[(size_t)k * NDEC];
        d2_s[tid] = fmaxf(acc + c2[tid], 0.f);
    }
    __syncthreads();

    {
        float part[NOUT];
        const float v = d2_s[tid];
        const float* w = D3 + (size_t)tid * NOUT;
#pragma unroll
        for (int o = 0; o < NOUT; o++) part[o] = v * w[o];
#pragma unroll
        for (int off = 16; off >= 1; off >>= 1)
#pragma unroll
            for (int o = 0; o < NOUT; o++)
                part[o] += __shfl_down_sync(0xffffffffu, part[o], off);
        if (lane == 0)
#pragma unroll
            for (int o = 0; o < NOUT; o++) wred[wrp * NOUT + o] = part[o];
    }
    __syncthreads();
    if (tid < NOUT) {
        float s = 0.f;
#pragma unroll
        for (int w = 0; w < 16; w++) s += wred[w * NOUT + tid];
        out[b * NOUT + tid] = c3[tid] + s;
    }
}

// ---------------------------------------------------------------------------
extern "C" void kernel_launch(void* const* d_in, const int* in_sizes, int n_in,
                              void* d_out, int out_size)
{
    (void)in_sizes; (void)n_in; (void)out_size;
    const float* x  = (const float*)d_in[0];
    const float* W1 = (const float*)d_in[1];
    const float* b1 = (const float*)d_in[2];
    const float* W2 = (const float*)d_in[3];
    const float* b2 = (const float*)d_in[4];
    const float* W3 = (const float*)d_in[5];
    const float* b3 = (const float*)d_in[6];
    const float* D1 = (const float*)d_in[7];
    const float* c1 = (const float*)d_in[8];
    const float* D2 = (const float*)d_in[9];
    const float* c2 = (const float*)d_in[10];
    const float* D3 = (const float*)d_in[11];
    const float* c3 = (const float*)d_in[12];

    cudaFuncSetAttribute(encoder_kernel, cudaFuncAttributeMaxDynamicSharedMemorySize, SMEM_TOTAL);

    convert_weights<<<320, 256>>>(W1, W2, W3);
    encoder_kernel<<<GRID_ENC, THREADS, SMEM_TOTAL>>>(x, b1, b2, b3);
    decoder_kernel<<<BATCH, 512>>>(D1, c1, D2, c2, D3, c3, (float*)d_out);
}